// round 5
// baseline (speedup 1.0000x reference)
#include <cuda_runtime.h>
#include <math.h>

// ---------------------------------------------------------------------------
// QANet forward, fp32 / f32x2 on sm_103a.
// LN fused into consumers; depthwise conv fused into pointwise GEMM loader.
// R5: 512-thread GEMM blocks (4e x 4l per thread) for occupancy.
// ---------------------------------------------------------------------------
#define kB 64
#define kD 128
#define kN 400
#define kM 50
#define kH 8
#define kKD 16
#define kNC 4
#define kKW 7
#define kPAD 3

typedef unsigned long long u64;

__device__ __forceinline__ u64 pk2(float lo, float hi) {
    u64 r; asm("mov.b64 %0,{%1,%2};" : "=l"(r) : "f"(lo), "f"(hi)); return r;
}
__device__ __forceinline__ void upk2(u64 v, float& lo, float& hi) {
    asm("mov.b64 {%0,%1},%2;" : "=f"(lo), "=f"(hi) : "l"(v));
}
__device__ __forceinline__ u64 fma2(u64 a, u64 b, u64 c) {
    u64 d; asm("fma.rn.f32x2 %0,%1,%2,%3;" : "=l"(d) : "l"(a), "l"(b), "l"(c)); return d;
}
__device__ __forceinline__ u64 mul2(u64 a, u64 b) {
    u64 d; asm("mul.rn.f32x2 %0,%1,%2;" : "=l"(d) : "l"(a), "l"(b)); return d;
}

// ------------------------- device scratch (static) -------------------------
__device__ float g_C[kB * kD * kN];
__device__ float g_Q[kB * kD * kM];
__device__ float g_dw[kB * kD * kN];
__device__ float g_Q2[kB * kD * kM];
__device__ float g_qkv[kB * 3 * kD * kN];
__device__ float g_ao[kB * kD * kN];
__device__ float g_Wqkv[3 * kD * kD];
__device__ float g_bqkv[3 * kD];
__device__ float g_pe[kD * kN];
__device__ float g_mu[kB * kN];
__device__ float g_ri[kB * kN];
__device__ float g_S[kB * kM * kN];
__device__ float g_Sr[kB * kM * kN];
__device__ float g_Sc[kB * kM * kN];
__device__ float g_U[kB * kM * kD];
__device__ float g_Ct[kB * kN * kD];
__device__ float g_Qt[kB * kM * kD];
__device__ float g_Qw[kB * kM * kD];
__device__ float g_cc[kB * kN];
__device__ float g_qq[kB * kM];

// ------------------------------ PE table ----------------------------------
__global__ void k_pe() {
    int idx = blockIdx.x * blockDim.x + threadIdx.x;
    if (idx >= kD * kN) return;
    int d = idx / kN;
    int l = idx % kN;
    int d0 = d & ~1;
    double f = pow(10000.0, -(double)d0 / (double)kD);
    double a = (double)l * f;
    g_pe[idx] = (d & 1) ? (float)cos(a) : (float)sin(a);
}

// ----------------- add PE + compute LN stats in one pass -------------------
__global__ void __launch_bounds__(128) k_add_pe_stats(const float* __restrict__ x,
                                                      float* __restrict__ y,
                                                      float* __restrict__ omu,
                                                      float* __restrict__ ori, int L) {
    int tid = threadIdx.x;
    int lsub = tid & 31;
    int grp = tid >> 5;
    int pos = blockIdx.x * 32 + lsub;
    int P = kB * L;
    bool ok = pos < P;
    int b = ok ? pos / L : 0;
    int l = ok ? pos % L : 0;

    float s = 0.f, sq = 0.f;
    if (ok) {
        const float* xp = x + ((size_t)b * kD + grp * 32) * L + l;
        float* yp = y + ((size_t)b * kD + grp * 32) * L + l;
#pragma unroll
        for (int k = 0; k < 32; k++) {
            int d = grp * 32 + k;
            float v = xp[(size_t)k * L] + g_pe[d * kN + l];
            yp[(size_t)k * L] = v;
            s += v;
            sq += v * v;
        }
    }
    __shared__ float ss[4][32], sb[4][32];
    ss[grp][lsub] = s;
    sb[grp][lsub] = sq;
    __syncthreads();
    if (grp == 0 && ok) {
        float ts = ss[0][lsub] + ss[1][lsub] + ss[2][lsub] + ss[3][lsub];
        float tq = sb[0][lsub] + sb[1][lsub] + sb[2][lsub] + sb[3][lsub];
        float mu = ts * (1.f / 128.f);
        float var = (tq - 128.f * mu * mu) * (1.f / 127.f);
        var = fmaxf(var, 0.f);
        omu[pos] = mu;
        ori[pos] = 1.f / (sqrtf(var) + 1e-6f);
    }
}

// ---------------- fused LN + depthwise conv + pointwise GEMM ----------------
// 512 threads: eq = tid>>4 (32 groups x 4e), lq = tid&15 (16 groups x 4l).
__global__ void __launch_bounds__(512, 2) k_cgemm(const float* __restrict__ X,
                                                  const float* __restrict__ Wpw,
                                                  const float* __restrict__ pwb,
                                                  const float* __restrict__ cw,
                                                  const float* __restrict__ cb,
                                                  const float* __restrict__ gamma,
                                                  const float* __restrict__ beta,
                                                  const float* __restrict__ mu,
                                                  const float* __restrict__ ri,
                                                  float* __restrict__ out,
                                                  float* __restrict__ omu,
                                                  float* __restrict__ ori, int L) {
    __shared__ float Xl[32][72];
    __shared__ float Xs[32][68];
    __shared__ float Ws[32][132];   // reused as stats reduction buffer at end
    __shared__ float mus[72], ris[72];
    __shared__ float gs[128], bs2[128];
    __shared__ float cws[128][8];

    int tid = threadIdx.x;
    int eq = tid >> 4;
    int lq = tid & 15;
    int l0 = blockIdx.x * 64;
    int b = blockIdx.z;

    if (tid < 70) {
        int gl = l0 + tid - 3;
        bool in = (gl >= 0 && gl < L);
        mus[tid] = in ? mu[(size_t)b * L + gl] : 0.f;
        ris[tid] = in ? ri[(size_t)b * L + gl] : 0.f;
    }
    if (tid < 128) {
        gs[tid] = gamma[tid];
        bs2[tid] = beta[tid];
#pragma unroll
        for (int k = 0; k < 7; k++) cws[tid][k] = cw[tid * 7 + k];
        cws[tid][7] = cb[tid];
    }
    __syncthreads();

    u64 acc[8] = {0, 0, 0, 0, 0, 0, 0, 0};

    for (int d0 = 0; d0 < 128; d0 += 32) {
        // LN'd halo tile (32 x 70)
#pragma unroll
        for (int r = 0; r < 5; r++) {
            int idx = tid + r * 512;
            if (idx < 32 * 70) {
                int dd = idx / 70;
                int ll = idx % 70;
                int gl = l0 + ll - 3;
                float v = 0.f;
                if (gl >= 0 && gl < L) {
                    float xv = X[((size_t)b * 128 + d0 + dd) * L + gl];
                    v = gs[d0 + dd] * (xv - mus[ll]) * ris[ll] + bs2[d0 + dd];
                }
                Xl[dd][ll] = v;
            }
        }
        // pw weights
#pragma unroll
        for (int r = 0; r < 8; r++) {
            int idx = tid + r * 512;
            int dd = idx & 31;
            int e = idx >> 5;
            Ws[dd][e] = Wpw[(size_t)e * 128 + d0 + dd];
        }
        __syncthreads();
        // depthwise conv
#pragma unroll
        for (int r = 0; r < 4; r++) {
            int idx = tid + r * 512;
            int dd = idx >> 6;
            int ll = idx & 63;
            int d = d0 + dd;
            float a = cws[d][7];
#pragma unroll
            for (int k = 0; k < 7; k++) a += cws[d][k] * Xl[dd][ll + k];
            Xs[dd][ll] = a;
        }
        __syncthreads();
        // main fma2 loop: 4e x 4l per thread
#pragma unroll
        for (int dd = 0; dd < 32; dd++) {
            float4 xv = *(const float4*)&Xs[dd][lq * 4];
            u64 x0 = pk2(xv.x, xv.x), x1 = pk2(xv.y, xv.y);
            u64 x2 = pk2(xv.z, xv.z), x3 = pk2(xv.w, xv.w);
            ulonglong2 wa = *(const ulonglong2*)&Ws[dd][eq * 4];
            acc[0] = fma2(wa.x, x0, acc[0]);
            acc[1] = fma2(wa.x, x1, acc[1]);
            acc[2] = fma2(wa.x, x2, acc[2]);
            acc[3] = fma2(wa.x, x3, acc[3]);
            acc[4] = fma2(wa.y, x0, acc[4]);
            acc[5] = fma2(wa.y, x1, acc[5]);
            acc[6] = fma2(wa.y, x2, acc[6]);
            acc[7] = fma2(wa.y, x3, acc[7]);
        }
        __syncthreads();
    }

    float sum_l[4] = {0.f, 0.f, 0.f, 0.f};
    float sq_l[4] = {0.f, 0.f, 0.f, 0.f};
#pragma unroll
    for (int p = 0; p < 2; p++) {
        int e0 = eq * 4 + 2 * p;
        float b0v = pwb[e0], b1v = pwb[e0 + 1];
#pragma unroll
        for (int q = 0; q < 4; q++) {
            float v0, v1;
            upk2(acc[p * 4 + q], v0, v1);
            v0 = fmaxf(v0 + b0v, 0.f);
            v1 = fmaxf(v1 + b1v, 0.f);
            int lg = l0 + lq * 4 + q;
            if (lg < L) {
                size_t oi0 = ((size_t)b * 128 + e0) * L + lg;
                size_t oi1 = oi0 + L;
                v0 += X[oi0];
                v1 += X[oi1];
                out[oi0] = v0;
                out[oi1] = v1;
            }
            sum_l[q] += v0 + v1;
            sq_l[q] += v0 * v0 + v1 * v1;
        }
    }
    // stats reduction: overlay on Ws (dead after last K-step sync)
    float* red = &Ws[0][0];   // red1: [32][64] at 0, red2: [32][64] at 2048
#pragma unroll
    for (int q = 0; q < 4; q++) {
        red[eq * 64 + lq * 4 + q] = sum_l[q];
        red[2048 + eq * 64 + lq * 4 + q] = sq_l[q];
    }
    __syncthreads();
    if (tid < 64) {
        int lg = l0 + tid;
        if (lg < L) {
            float s = 0.f, ss = 0.f;
#pragma unroll
            for (int g = 0; g < 32; g++) {
                s += red[g * 64 + tid];
                ss += red[2048 + g * 64 + tid];
            }
            float muv = s * (1.f / 128.f);
            float var = (ss - 128.f * muv * muv) * (1.f / 127.f);
            var = fmaxf(var, 0.f);
            omu[(size_t)b * L + lg] = muv;
            ori[(size_t)b * L + lg] = 1.f / (sqrtf(var) + 1e-6f);
        }
    }
}

// ------------------------------- GEMM --------------------------------------
// 512 threads: eq = tid>>4 (32 groups x 4e), lq = tid&15 (16 groups x 4l).
template <bool TR, bool RELU, bool RES, bool LNX, bool STATS>
__global__ void __launch_bounds__(512, 2) k_gemm(const float* __restrict__ X,
                                                 const float* __restrict__ W,
                                                 const float* __restrict__ bias,
                                                 const float* res, float* out,
                                                 int L, int Etot,
                                                 const float* __restrict__ mu,
                                                 const float* __restrict__ ri,
                                                 const float* __restrict__ gamma,
                                                 const float* __restrict__ beta,
                                                 float* omu, float* ori) {
    __shared__ float Xs[32][68];
    __shared__ float Ws[32][132];   // reused as stats reduction buffer
    __shared__ float mus[64], ris[64];
    __shared__ float gs[128], bs2[128];

    int tid = threadIdx.x;
    int eq = tid >> 4;
    int lq = tid & 15;
    int l0 = blockIdx.x * 64;
    int et = blockIdx.y * 128;
    int b = blockIdx.z;

    if (LNX) {
        if (tid < 64) {
            int p = l0 + tid;
            mus[tid] = (p < L) ? mu[(size_t)b * L + p] : 0.f;
            ris[tid] = (p < L) ? ri[(size_t)b * L + p] : 0.f;
        }
        if (tid < 128) {
            gs[tid] = gamma[tid];
            bs2[tid] = beta[tid];
        }
        __syncthreads();
    }

    u64 acc[8] = {0, 0, 0, 0, 0, 0, 0, 0};

    for (int d0 = 0; d0 < 128; d0 += 32) {
#pragma unroll
        for (int r = 0; r < 4; r++) {
            int idx = tid + r * 512;
            int dd = idx >> 6;
            int ll = idx & 63;
            int lg = l0 + ll;
            float v = 0.f;
            if (lg < L) {
                v = X[((size_t)b * 128 + d0 + dd) * L + lg];
                if (LNX) v = gs[d0 + dd] * (v - mus[ll]) * ris[ll] + bs2[d0 + dd];
            }
            Xs[dd][ll] = v;
        }
#pragma unroll
        for (int r = 0; r < 8; r++) {
            int idx = tid + r * 512;
            if (TR) {
                int dd = idx >> 7;
                int e = idx & 127;
                Ws[dd][e] = W[(size_t)(d0 + dd) * Etot + et + e];
            } else {
                int dd = idx & 31;
                int e = idx >> 5;
                Ws[dd][e] = W[(size_t)(et + e) * 128 + d0 + dd];
            }
        }
        __syncthreads();
#pragma unroll
        for (int dd = 0; dd < 32; dd++) {
            float4 xv = *(const float4*)&Xs[dd][lq * 4];
            u64 x0 = pk2(xv.x, xv.x), x1 = pk2(xv.y, xv.y);
            u64 x2 = pk2(xv.z, xv.z), x3 = pk2(xv.w, xv.w);
            ulonglong2 wa = *(const ulonglong2*)&Ws[dd][eq * 4];
            acc[0] = fma2(wa.x, x0, acc[0]);
            acc[1] = fma2(wa.x, x1, acc[1]);
            acc[2] = fma2(wa.x, x2, acc[2]);
            acc[3] = fma2(wa.x, x3, acc[3]);
            acc[4] = fma2(wa.y, x0, acc[4]);
            acc[5] = fma2(wa.y, x1, acc[5]);
            acc[6] = fma2(wa.y, x2, acc[6]);
            acc[7] = fma2(wa.y, x3, acc[7]);
        }
        __syncthreads();
    }

    float sum_l[4] = {0.f, 0.f, 0.f, 0.f};
    float sq_l[4] = {0.f, 0.f, 0.f, 0.f};
#pragma unroll
    for (int p = 0; p < 2; p++) {
        int e0 = et + eq * 4 + 2 * p;
        float b0v = bias[e0], b1v = bias[e0 + 1];
#pragma unroll
        for (int q = 0; q < 4; q++) {
            float v0, v1;
            upk2(acc[p * 4 + q], v0, v1);
            v0 += b0v;
            v1 += b1v;
            if (RELU) { v0 = fmaxf(v0, 0.f); v1 = fmaxf(v1, 0.f); }
            int lg = l0 + lq * 4 + q;
            if (lg < L) {
                size_t oi0 = ((size_t)b * Etot + e0) * L + lg;
                size_t oi1 = oi0 + L;
                if (RES) { v0 += res[oi0]; v1 += res[oi1]; }
                out[oi0] = v0;
                out[oi1] = v1;
            }
            if (STATS) {
                sum_l[q] += v0 + v1;
                sq_l[q] += v0 * v0 + v1 * v1;
            }
        }
    }
    if (STATS) {
        float* red = &Ws[0][0];
#pragma unroll
        for (int q = 0; q < 4; q++) {
            red[eq * 64 + lq * 4 + q] = sum_l[q];
            red[2048 + eq * 64 + lq * 4 + q] = sq_l[q];
        }
        __syncthreads();
        if (tid < 64) {
            int lg = l0 + tid;
            if (lg < L) {
                float s = 0.f, ss = 0.f;
#pragma unroll
                for (int g = 0; g < 32; g++) {
                    s += red[g * 64 + tid];
                    ss += red[2048 + g * 64 + tid];
                }
                float muv = s * (1.f / 128.f);
                float var = (ss - 128.f * muv * muv) * (1.f / 127.f);
                var = fmaxf(var, 0.f);
                omu[(size_t)b * L + lg] = muv;
                ori[(size_t)b * L + lg] = 1.f / (sqrtf(var) + 1e-6f);
            }
        }
    }
}

// ----------------------------- QKV packing ---------------------------------
__global__ void k_pack_qkv(const float* __restrict__ Wq, const float* __restrict__ Wk,
                           const float* __restrict__ Wv, const float* __restrict__ bq,
                           const float* __restrict__ bk, const float* __restrict__ bv) {
    int idx = blockIdx.x * blockDim.x + threadIdx.x;
    if (idx < 3 * 128 * 128) {
        int e = idx >> 7;
        int d = idx & 127;
        int qv = e >> 7;
        int hk = e & 127;
        int h = hk >> 4;
        int kk = hk & 15;
        const float* src = (qv == 0) ? Wq : (qv == 1 ? Wk : Wv);
        g_Wqkv[idx] = src[((size_t)h * 128 + d) * 16 + kk];
    }
    if (idx < 384) {
        int qv = idx >> 7;
        int hk = idx & 127;
        const float* srcb = (qv == 0) ? bq : (qv == 1 ? bk : bv);
        g_bqkv[idx] = srcb[hk];
    }
}

// ----------------------------- attention core ------------------------------
__global__ void __launch_bounds__(256) k_attn(const float* __restrict__ qkv,
                                              const float* __restrict__ mask,
                                              float* __restrict__ o, int L) {
    const int KT = 64;
    __shared__ u64 ks[KT][9], vs[KT][9];
    __shared__ float ms[KT];
    int tid = threadIdx.x;
    int bh = blockIdx.y;
    int b = bh >> 3;
    int h = bh & 7;
    int i = blockIdx.x * 256 + tid;
    bool act = i < L;

    u64 q2[8];
    if (act) {
        const float* qp = qkv + ((size_t)b * 384 + h * 16) * L + i;
#pragma unroll
        for (int c = 0; c < 8; c++)
            q2[c] = pk2(qp[(size_t)(2 * c) * L] * 0.25f, qp[(size_t)(2 * c + 1) * L] * 0.25f);
    }
    float m = -INFINITY, lsum = 0.f;
    u64 acc[8] = {0, 0, 0, 0, 0, 0, 0, 0};

    for (int j0 = 0; j0 < L; j0 += KT) {
        int cnt = min(KT, L - j0);
        for (int idx = tid; idx < 8 * KT; idx += 256) {
            int c = idx >> 6;
            int t = idx & 63;
            if (t < cnt) {
                const float* kp = qkv + ((size_t)b * 384 + 128 + h * 16 + 2 * c) * L + j0 + t;
                ks[t][c] = pk2(kp[0], kp[(size_t)L]);
                const float* vp = kp + (size_t)128 * L;
                vs[t][c] = pk2(vp[0], vp[(size_t)L]);
            } else {
                ks[t][c] = 0;
                vs[t][c] = 0;
            }
        }
        if (tid < KT) ms[tid] = (tid < cnt) ? mask[(size_t)b * L + j0 + tid] : 0.f;
        __syncthreads();
        if (act) {
            for (int g = 0; g < cnt; g += 8) {
                float sreg[8];
#pragma unroll
                for (int t2 = 0; t2 < 8; t2++) {
                    int t = g + t2;
                    u64 s2 = 0;
#pragma unroll
                    for (int c = 0; c < 8; c++) s2 = fma2(q2[c], ks[t][c], s2);
                    float slo, shi;
                    upk2(s2, slo, shi);
                    sreg[t2] = slo + shi - 1e30f * (1.f - ms[t]);
                }
                float gm = sreg[0];
#pragma unroll
                for (int t2 = 1; t2 < 8; t2++) gm = fmaxf(gm, sreg[t2]);
                float nm = fmaxf(m, gm);
                float sc = __expf(m - nm);
                lsum *= sc;
                u64 scp = pk2(sc, sc);
#pragma unroll
                for (int c = 0; c < 8; c++) acc[c] = mul2(scp, acc[c]);
#pragma unroll
                for (int t2 = 0; t2 < 8; t2++) {
                    int t = g + t2;
                    float p = __expf(sreg[t2] - nm);
                    lsum += p;
                    u64 pp = pk2(p, p);
#pragma unroll
                    for (int c = 0; c < 8; c++) acc[c] = fma2(pp, vs[t][c], acc[c]);
                }
                m = nm;
            }
        }
        __syncthreads();
    }
    if (act) {
        float r = 1.f / lsum;
        float* op = o + ((size_t)b * 128 + h * 16) * L + i;
#pragma unroll
        for (int c = 0; c < 8; c++) {
            float lo, hi;
            upk2(acc[c], lo, hi);
            op[(size_t)(2 * c) * L] = lo * r;
            op[(size_t)(2 * c + 1) * L] = hi * r;
        }
    }
}

// ------------------------------ transposes ---------------------------------
__global__ void k_trC(const float* __restrict__ X, float* __restrict__ Y, int L) {
    __shared__ float t[32][33];
    int b = blockIdx.z, d0 = blockIdx.y * 32, l0 = blockIdx.x * 32;
    int tx = threadIdx.x, ty = threadIdx.y;
#pragma unroll
    for (int k = 0; k < 4; k++) {
        int l = l0 + tx;
        t[ty + 8 * k][tx] = (l < L) ? X[((size_t)b * 128 + d0 + ty + 8 * k) * L + l] : 0.f;
    }
    __syncthreads();
#pragma unroll
    for (int k = 0; k < 4; k++) {
        int l = l0 + ty + 8 * k;
        if (l < L) Y[((size_t)b * L + l) * 128 + d0 + tx] = t[tx][ty + 8 * k];
    }
}

__global__ void k_trQ(const float* __restrict__ X, float* __restrict__ Yt,
                      float* __restrict__ Yw, const float* __restrict__ wm) {
    __shared__ float t[32][33];
    int b = blockIdx.z, d0 = blockIdx.y * 32, l0 = blockIdx.x * 32;
    int tx = threadIdx.x, ty = threadIdx.y;
#pragma unroll
    for (int k = 0; k < 4; k++) {
        int l = l0 + tx;
        t[ty + 8 * k][tx] = (l < kM) ? X[((size_t)b * 128 + d0 + ty + 8 * k) * kM + l] : 0.f;
    }
    __syncthreads();
    float w = wm[d0 + tx];
#pragma unroll
    for (int k = 0; k < 4; k++) {
        int l = l0 + ty + 8 * k;
        if (l < kM) {
            float v = t[tx][ty + 8 * k];
            size_t oi = ((size_t)b * kM + l) * 128 + d0 + tx;
            Yt[oi] = v;
            Yw[oi] = v * w;
        }
    }
}

// ------------------------------ CQ attention -------------------------------
__global__ void k_dot(const float* __restrict__ X, const float* __restrict__ w,
                      float* __restrict__ out, int L) {
    int idx = blockIdx.x * blockDim.x + threadIdx.x;
    if (idx >= kB * L) return;
    int b = idx / L;
    int pos = idx % L;
    const float* xp = X + (size_t)b * kD * L + pos;
    float a = 0.f;
#pragma unroll 8
    for (int d = 0; d < kD; d++) a += w[d] * xp[(size_t)d * L];
    out[idx] = a;
}

__global__ void __launch_bounds__(256) k_sgemm(const float* __restrict__ X,
                                               const float* __restrict__ Qw,
                                               const float* __restrict__ cc,
                                               const float* __restrict__ qq,
                                               const float* __restrict__ b0,
                                               float* __restrict__ S) {
    __shared__ float Xs[32][33];
    __shared__ float Ws[32][68];
    int tid = threadIdx.x;
    int l = tid & 31;
    int eg = tid >> 5;
    int l0 = blockIdx.x * 32;
    int b = blockIdx.y;
    u64 acc[4] = {0, 0, 0, 0};

    for (int d0 = 0; d0 < 128; d0 += 32) {
#pragma unroll
        for (int r = 0; r < 4; r++) {
            int idx = tid + r * 256;
            int dd = idx >> 5, ll = idx & 31;
            int lg = l0 + ll;
            Xs[dd][ll] = (lg < kN) ? X[((size_t)b * 128 + d0 + dd) * kN + lg] : 0.f;
        }
#pragma unroll
        for (int r = 0; r < 8; r++) {
            int idx = tid + r * 256;
            int dd = idx >> 6;
            int e = idx & 63;
            Ws[dd][e] = (e < kM) ? Qw[((size_t)b * kM + e) * 128 + d0 + dd] : 0.f;
        }
        __syncthreads();
#pragma unroll
        for (int dd = 0; dd < 32; dd++) {
            float xv = Xs[dd][l];
            u64 xx = pk2(xv, xv);
            const ulonglong2* wr = (const ulonglong2*)&Ws[dd][eg * 8];
            ulonglong2 w0 = wr[0], w1 = wr[1];
            acc[0] = fma2(xx, w0.x, acc[0]);
            acc[1] = fma2(xx, w0.y, acc[1]);
            acc[2] = fma2(xx, w1.x, acc[2]);
            acc[3] = fma2(xx, w1.y, acc[3]);
        }
        __syncthreads();
    }
    int lg = l0 + l;
    if (lg < kN) {
        float base = cc[b * kN + lg] + b0[0];
#pragma unroll
        for (int j = 0; j < 4; j++) {
            float v0, v1;
            upk2(acc[j], v0, v1);
            int e0 = eg * 8 + 2 * j;
            if (e0 < kM) S[((size_t)b * kM + e0) * kN + lg] = v0 + base + qq[b * kM + e0];
            if (e0 + 1 < kM) S[((size_t)b * kM + e0 + 1) * kN + lg] = v1 + base + qq[b * kM + e0 + 1];
        }
    }
}

__global__ void k_smrow(const float* __restrict__ qmask) {
    int idx = blockIdx.x * blockDim.x + threadIdx.x;
    if (idx >= kB * kN) return;
    int b = idx / kN;
    int n = idx % kN;
    float v[kM];
    float mx = -INFINITY;
#pragma unroll
    for (int m = 0; m < kM; m++) {
        v[m] = g_S[((size_t)b * kM + m) * kN + n] - 1e30f * (1.f - qmask[b * kM + m]);
        mx = fmaxf(mx, v[m]);
    }
    float s = 0.f;
#pragma unroll
    for (int m = 0; m < kM; m++) {
        v[m] = __expf(v[m] - mx);
        s += v[m];
    }
    float r = 1.f / s;
#pragma unroll
    for (int m = 0; m < kM; m++) g_Sr[((size_t)b * kM + m) * kN + n] = v[m] * r;
}

__global__ void k_smcol(const float* __restrict__ cmask) {
    int w = (blockIdx.x * blockDim.x + threadIdx.x) >> 5;
    int lane = threadIdx.x & 31;
    if (w >= kB * kM) return;
    int b = w / kM;
    const float* row = g_S + (size_t)w * kN;
    const float* mrow = cmask + (size_t)b * kN;
    float v[13];
#pragma unroll
    for (int k = 0; k < 13; k++) {
        int n = lane + k * 32;
        v[k] = (n < kN) ? row[n] - 1e30f * (1.f - mrow[n]) : -INFINITY;
    }
    float mx = v[0];
#pragma unroll
    for (int k = 1; k < 13; k++) mx = fmaxf(mx, v[k]);
#pragma unroll
    for (int o = 16; o; o >>= 1) mx = fmaxf(mx, __shfl_xor_sync(0xffffffff, mx, o));
    float s = 0.f;
    float e[13];
#pragma unroll
    for (int k = 0; k < 13; k++) {
        int n = lane + k * 32;
        e[k] = (n < kN) ? __expf(v[k] - mx) : 0.f;
        s += e[k];
    }
#pragma unroll
    for (int o = 16; o; o >>= 1) s += __shfl_xor_sync(0xffffffff, s, o);
    float r = 1.f / s;
    float* orow = g_Sc + (size_t)w * kN;
#pragma unroll
    for (int k = 0; k < 13; k++) {
        int n = lane + k * 32;
        if (n < kN) orow[n] = e[k] * r;
    }
}

__global__ void __launch_bounds__(512) k_U(const float* __restrict__ Ct) {
    int b = blockIdx.x;
    int tid = threadIdx.x;
    int d = tid & 127;
    int mq = tid >> 7;
    __shared__ float cts[16][128];
    __shared__ float scs[16][56];
    u64 acc[7] = {0, 0, 0, 0, 0, 0, 0};

    for (int n0 = 0; n0 < kN; n0 += 16) {
#pragma unroll
        for (int r = 0; r < 4; r++) {
            int idx = tid + r * 512;
            int n = idx >> 7, dd = idx & 127;
            cts[n][dd] = Ct[((size_t)b * kN + n0 + n) * 128 + dd];
        }
        for (int idx = tid; idx < 16 * 56; idx += 512) {
            int n = idx & 15;
            int m = idx >> 4;
            scs[n][m] = (m < kM) ? g_Sc[((size_t)b * kM + m) * kN + n0 + n] : 0.f;
        }
        __syncthreads();
#pragma unroll
        for (int n = 0; n < 16; n++) {
            float ct = cts[n][d];
            u64 c2 = pk2(ct, ct);
            const u64* sp = (const u64*)&scs[n][mq * 14];
#pragma unroll
            for (int j = 0; j < 7; j++) acc[j] = fma2(c2, sp[j], acc[j]);
        }
        __syncthreads();
    }
#pragma unroll
    for (int j = 0; j < 7; j++) {
        float v0, v1;
        upk2(acc[j], v0, v1);
        int m = mq * 14 + 2 * j;
        if (m < kM) g_U[((size_t)b * kM + m) * 128 + d] = v0;
        if (m + 1 < kM) g_U[((size_t)b * kM + m + 1) * 128 + d] = v1;
    }
}

__global__ void __launch_bounds__(256) k_out(const float* __restrict__ Ct,
                                             float* __restrict__ out) {
    int b = blockIdx.x / 25;
    int n0 = (blockIdx.x % 25) * 16;
    int tid = threadIdx.x;
    int d = tid & 127;
    int nq = tid >> 7;
    __shared__ float srs[kM][16];
    for (int idx = tid; idx < kM * 16; idx += 256) {
        int m = idx >> 4, nj = idx & 15;
        srs[m][nj] = g_Sr[((size_t)b * kM + m) * kN + n0 + nj];
    }
    __syncthreads();
    u64 a2[4] = {0, 0, 0, 0};
    u64 b2[4] = {0, 0, 0, 0};
    for (int m = 0; m < kM; m++) {
        float qv = g_Qt[((size_t)b * kM + m) * 128 + d];
        float uv = g_U[((size_t)b * kM + m) * 128 + d];
        u64 q2 = pk2(qv, qv), u2 = pk2(uv, uv);
        const u64* sp = (const u64*)&srs[m][nq * 8];
#pragma unroll
        for (int j = 0; j < 4; j++) {
            a2[j] = fma2(sp[j], q2, a2[j]);
            b2[j] = fma2(sp[j], u2, b2[j]);
        }
    }
#pragma unroll
    for (int j = 0; j < 4; j++) {
        float a0, a1, bt0, bt1;
        upk2(a2[j], a0, a1);
        upk2(b2[j], bt0, bt1);
#pragma unroll
        for (int t = 0; t < 2; t++) {
            int n = n0 + nq * 8 + 2 * j + t;
            float a = (t == 0) ? a0 : a1;
            float bt = (t == 0) ? bt0 : bt1;
            float c = Ct[((size_t)b * kN + n) * 128 + d];
            size_t base = ((size_t)b * kN + n) * 512;
            out[base + d] = c;
            out[base + 128 + d] = a;
            out[base + 256 + d] = c * a;
            out[base + 384 + d] = c * bt;
        }
    }
}

// ------------------------------- host side ---------------------------------
static inline int ceil_div(int a, int b) { return (a + b - 1) / b; }

extern "C" void kernel_launch(void* const* d_in, const int* in_sizes, int n_in,
                              void* d_out, int out_size) {
    (void)in_sizes; (void)n_in; (void)out_size;
    const float* ctx   = (const float*)d_in[0];
    const float* qst   = (const float*)d_in[1];
    const float* cmask = (const float*)d_in[2];
    const float* qmask = (const float*)d_in[3];
    const float* ln_g  = (const float*)d_in[4];
    const float* ln_b  = (const float*)d_in[5];
    const float* dww   = (const float*)d_in[6];
    const float* dwb   = (const float*)d_in[7];
    const float* pww   = (const float*)d_in[8];
    const float* pwb   = (const float*)d_in[9];
    const float* Wq    = (const float*)d_in[10];
    const float* bq    = (const float*)d_in[11];
    const float* Wk    = (const float*)d_in[12];
    const float* bk    = (const float*)d_in[13];
    const float* Wv    = (const float*)d_in[14];
    const float* bv    = (const float*)d_in[15];
    const float* Wo    = (const float*)d_in[16];
    const float* bo    = (const float*)d_in[17];
    const float* Wfc   = (const float*)d_in[18];
    const float* bfc   = (const float*)d_in[19];
    const float* cq_wc = (const float*)d_in[20];
    const float* cq_wq = (const float*)d_in[21];
    const float* cq_wm = (const float*)d_in[22];
    const float* cq_b  = (const float*)d_in[23];

    float *pC, *pQ, *pdw, *pQ2, *pqkv, *pao, *pcc, *pqq, *pCt, *pQt, *pQw, *pmu, *pri;
    cudaGetSymbolAddress((void**)&pC, g_C);
    cudaGetSymbolAddress((void**)&pQ, g_Q);
    cudaGetSymbolAddress((void**)&pdw, g_dw);
    cudaGetSymbolAddress((void**)&pQ2, g_Q2);
    cudaGetSymbolAddress((void**)&pqkv, g_qkv);
    cudaGetSymbolAddress((void**)&pao, g_ao);
    cudaGetSymbolAddress((void**)&pcc, g_cc);
    cudaGetSymbolAddress((void**)&pqq, g_qq);
    cudaGetSymbolAddress((void**)&pCt, g_Ct);
    cudaGetSymbolAddress((void**)&pQt, g_Qt);
    cudaGetSymbolAddress((void**)&pQw, g_Qw);
    cudaGetSymbolAddress((void**)&pmu, g_mu);
    cudaGetSymbolAddress((void**)&pri, g_ri);
    float* pWqkv; cudaGetSymbolAddress((void**)&pWqkv, g_Wqkv);
    float* pbqkv; cudaGetSymbolAddress((void**)&pbqkv, g_bqkv);
    float* pS; cudaGetSymbolAddress((void**)&pS, g_S);

    k_pe<<<ceil_div(kD * kN, 256), 256>>>();
    k_pack_qkv<<<ceil_div(3 * 128 * 128, 256), 256>>>(Wq, Wk, Wv, bq, bk, bv);

    auto run_block = [&](const float* emb, float* act, float* alt, const float* msk, int L) {
        int lt = ceil_div(L, 64);
        k_add_pe_stats<<<ceil_div(kB * L, 32), 128>>>(emb, act, pmu, pri, L);
        float* bufs[2] = {act, alt};
        for (int i = 0; i < kNC; i++) {
            float* src = bufs[i & 1];
            float* dst = bufs[(i + 1) & 1];
            k_cgemm<<<dim3(lt, 1, kB), 512>>>(
                src, pww + (size_t)i * kD * kD, pwb + (size_t)i * kD,
                dww + (size_t)i * kD * kKW, dwb + (size_t)i * kD,
                ln_g, ln_b, pmu, pri, dst, pmu, pri, L);
        }
        k_gemm<false, false, false, true, false><<<dim3(lt, 3, kB), 512>>>(
            act, pWqkv, pbqkv, nullptr, pqkv, L, 384, pmu, pri, ln_g, ln_b, nullptr, nullptr);
        k_attn<<<dim3(ceil_div(L, 256), kB * kH), 256>>>(pqkv, msk, pao, L);
        k_gemm<true, false, true, false, true><<<dim3(lt, 1, kB), 512>>>(
            pao, Wo, bo, act, act, L, kD, nullptr, nullptr, nullptr, nullptr, pmu, pri);
        k_gemm<false, false, true, true, false><<<dim3(lt, 1, kB), 512>>>(
            act, Wfc, bfc, act, act, L, kD, pmu, pri, ln_g, ln_b, nullptr, nullptr);
    };

    run_block(ctx, pC, pdw, cmask, kN);
    run_block(qst, pQ, pQ2, qmask, kM);

    // --------- context-query attention ---------
    k_dot<<<ceil_div(kB * kN, 256), 256>>>(pC, cq_wc, pcc, kN);
    k_dot<<<ceil_div(kB * kM, 256), 256>>>(pQ, cq_wq, pqq, kM);
    k_trC<<<dim3(13, 4, kB), dim3(32, 8)>>>(pC, pCt, kN);
    k_trQ<<<dim3(2, 4, kB), dim3(32, 8)>>>(pQ, pQt, pQw, cq_wm);
    k_sgemm<<<dim3(13, kB), 256>>>(pC, pQw, pcc, pqq, cq_b, pS);
    k_smrow<<<ceil_div(kB * kN, 256), 256>>>(qmask);
    k_smcol<<<ceil_div(kB * kM * 32, 256), 256>>>(cmask);
    k_U<<<kB, 512>>>(pCt);
    k_out<<<kB * 25, 256>>>(pCt, (float*)d_out);
}